// round 2
// baseline (speedup 1.0000x reference)
#include <cuda_runtime.h>
#include <cstdint>

#define N_NODES 8192
#define FIN     512
#define FOUT    256
#define ALPHA_S 0.2f
#define NEG_INF_S (-9e15f)

// ---- scratch (static device memory; no allocation) ----
__device__ __align__(16) float g_h [N_NODES * FOUT];
__device__ __align__(16) float g_s1[N_NODES];
__device__ __align__(16) float g_s2[N_NODES];
__device__ __align__(16) float g_m [N_NODES];

// ---- packed f32x2 helpers ----
__device__ __forceinline__ unsigned long long pack2(float lo, float hi) {
    unsigned long long r;
    asm("mov.b64 %0, {%1, %2};" : "=l"(r) : "f"(lo), "f"(hi));
    return r;
}
__device__ __forceinline__ void unpack2(unsigned long long v, float& lo, float& hi) {
    asm("mov.b64 {%0, %1}, %2;" : "=f"(lo), "=f"(hi) : "l"(v));
}

// ============================================================
// Kernel 1: h = input @ W   (8192x512 @ 512x256)
// BM=128, BN=128, BK=16, 256 threads, 8x8 microtile
// ============================================================
#define G1_BM 128
#define G1_BN 128
#define G1_BK 16

__global__ __launch_bounds__(256) void gemm_h_kernel(
    const float* __restrict__ A, const float* __restrict__ B, float* __restrict__ C)
{
    __shared__ float As[G1_BK][G1_BM + 4];
    __shared__ float Bs[G1_BK][G1_BN + 4];

    const int row0 = blockIdx.x * G1_BM;
    const int col0 = blockIdx.y * G1_BN;
    const int tid = threadIdx.x;
    const int tx = tid & 15, ty = tid >> 4;

    float acc[8][8];
#pragma unroll
    for (int i = 0; i < 8; i++)
#pragma unroll
        for (int j = 0; j < 8; j++) acc[i][j] = 0.f;

    for (int k0 = 0; k0 < FIN; k0 += G1_BK) {
        // A tile: 128x16 = 512 float4, 2 per thread
#pragma unroll
        for (int it = 0; it < 2; it++) {
            int i = tid + it * 256;          // 0..511
            int r = i >> 2;                  // row 0..127
            int c4 = i & 3;                  // which float4 in the 16
            float4 v = *(const float4*)&A[(row0 + r) * FIN + k0 + c4 * 4];
            As[c4 * 4 + 0][r] = v.x;
            As[c4 * 4 + 1][r] = v.y;
            As[c4 * 4 + 2][r] = v.z;
            As[c4 * 4 + 3][r] = v.w;
        }
        // B tile: 16x128 = 512 float4, 2 per thread
#pragma unroll
        for (int it = 0; it < 2; it++) {
            int i = tid + it * 256;          // 0..511
            int r = i >> 5;                  // k row 0..15
            int c4 = i & 31;                 // float4 col
            float4 v = *(const float4*)&B[(k0 + r) * FOUT + col0 + c4 * 4];
            *(float4*)&Bs[r][c4 * 4] = v;
        }
        __syncthreads();

#pragma unroll
        for (int k = 0; k < G1_BK; k++) {
            float af[8], bf[8];
#pragma unroll
            for (int i = 0; i < 8; i++) af[i] = As[k][ty * 8 + i];
#pragma unroll
            for (int j = 0; j < 8; j++) bf[j] = Bs[k][tx * 8 + j];
#pragma unroll
            for (int i = 0; i < 8; i++)
#pragma unroll
                for (int j = 0; j < 8; j++) acc[i][j] = fmaf(af[i], bf[j], acc[i][j]);
        }
        __syncthreads();
    }

#pragma unroll
    for (int i = 0; i < 8; i++) {
        int r = row0 + ty * 8 + i;
#pragma unroll
        for (int j4 = 0; j4 < 2; j4++) {
            float4 v = make_float4(acc[i][j4 * 4 + 0], acc[i][j4 * 4 + 1],
                                   acc[i][j4 * 4 + 2], acc[i][j4 * 4 + 3]);
            *(float4*)&C[r * FOUT + col0 + tx * 8 + j4 * 4] = v;
        }
    }
}

// ============================================================
// Kernel 2: s1[i] = h[i,:] . a[:F],  s2[i] = h[i,:] . a[F:]
// one warp per row
// ============================================================
__global__ __launch_bounds__(256) void s_kernel(
    const float* __restrict__ h, const float* __restrict__ a,
    float* __restrict__ s1, float* __restrict__ s2)
{
    int row = blockIdx.x * 8 + (threadIdx.x >> 5);
    int lane = threadIdx.x & 31;
    float a1 = 0.f, a2 = 0.f;
#pragma unroll
    for (int c = lane; c < FOUT; c += 32) {
        float hv = h[row * FOUT + c];
        a1 = fmaf(hv, a[c], a1);
        a2 = fmaf(hv, a[FOUT + c], a2);
    }
#pragma unroll
    for (int o = 16; o; o >>= 1) {
        a1 += __shfl_xor_sync(0xffffffffu, a1, o);
        a2 += __shfl_xor_sync(0xffffffffu, a2, o);
    }
    if (lane == 0) { s1[row] = a1; s2[row] = a2; }
}

// ============================================================
// Kernel 3: per-row softmax max.
// m_i = lrelu(s1_i + max_{j: adj_ij>0} s2_j)  (NEG_INF if no neighbor)
// ============================================================
__global__ __launch_bounds__(256) void rowmax_kernel(
    const int* __restrict__ adj, const float* __restrict__ s1,
    const float* __restrict__ s2, float* __restrict__ m_out)
{
    const int row = blockIdx.x;
    const int4* arow = (const int4*)(adj + row * N_NODES);
    const float4* s24 = (const float4*)s2;
    float mx = -__int_as_float(0x7f800000);  // -inf
    for (int j4 = threadIdx.x; j4 < N_NODES / 4; j4 += 256) {
        int4 av = arow[j4];
        float4 sv = s24[j4];
        if (av.x > 0) mx = fmaxf(mx, sv.x);
        if (av.y > 0) mx = fmaxf(mx, sv.y);
        if (av.z > 0) mx = fmaxf(mx, sv.z);
        if (av.w > 0) mx = fmaxf(mx, sv.w);
    }
    __shared__ float red[256];
    red[threadIdx.x] = mx;
    __syncthreads();
#pragma unroll
    for (int s = 128; s; s >>= 1) {
        if (threadIdx.x < s) red[threadIdx.x] = fmaxf(red[threadIdx.x], red[threadIdx.x + s]);
        __syncthreads();
    }
    if (threadIdx.x == 0) {
        float M = red[0];
        float m;
        if (isinf(M)) {
            m = NEG_INF_S;                 // no neighbors: max score is NEG_INF
        } else {
            float e = s1[row] + M;
            m = (e > 0.f) ? e : ALPHA_S * e;
        }
        m_out[row] = m;
    }
}

// ============================================================
// Kernel 4: fused attention GEMM + softmax normalize + ELU
// out[i,:] = elu( (sum_j p~_ij h_j) / (sum_j p~_ij) ),
// p~_ij = exp(score_ij - m_i)
// BM=64 rows, BN=256 (full F), BK=32; 256 threads, 4x16 microtile (f32x2)
// ============================================================
#define A_BM 64
#define A_BK 32

__global__ __launch_bounds__(256) void attn_kernel(
    const int* __restrict__ adj, const float* __restrict__ h,
    const float* __restrict__ s1v, const float* __restrict__ s2v,
    const float* __restrict__ mrow, float* __restrict__ out)
{
    __shared__ float Ps[A_BK][A_BM + 4];
    __shared__ float Hs[A_BK][FOUT];
    __shared__ float zred[256];
    __shared__ float zrow[A_BM];

    const int tid = threadIdx.x;
    const int tx = tid & 15, ty = tid >> 4;
    const int row0 = blockIdx.x * A_BM;

    const int pr = tid >> 2;       // P-compute row 0..63
    const int pg = tid & 3;        // j group (8 j's each)
    const float s1r = s1v[row0 + pr];
    const float mr  = mrow[row0 + pr];
    float zpart = 0.f;

    unsigned long long acc[4][8];
#pragma unroll
    for (int i = 0; i < 4; i++)
#pragma unroll
        for (int j = 0; j < 8; j++) acc[i][j] = 0ULL;

    const float* adjrow = nullptr; (void)adjrow;

    for (int j0 = 0; j0 < N_NODES; j0 += A_BK) {
        // ---- load H tile 32x256 (2048 float4, 8 per thread) ----
#pragma unroll
        for (int it = 0; it < 8; it++) {
            int idx = tid + it * 256;           // 0..2047
            int r = idx >> 6;                   // k row 0..31
            int c = (idx & 63) << 2;            // col
            *(float4*)&Hs[r][c] = *(const float4*)&h[(j0 + r) * FOUT + c];
        }
        // ---- compute P tile (transposed): Ps[jl][row] ----
#pragma unroll
        for (int q = 0; q < 2; q++) {
            int jl = pg * 8 + q * 4;
            int gj = j0 + jl;
            int4 av = *(const int4*)&adj[(row0 + pr) * N_NODES + gj];
            float4 sv = *(const float4*)&s2v[gj];
            float e0 = s1r + sv.x; e0 = (e0 > 0.f) ? e0 : ALPHA_S * e0;
            float e1 = s1r + sv.y; e1 = (e1 > 0.f) ? e1 : ALPHA_S * e1;
            float e2 = s1r + sv.z; e2 = (e2 > 0.f) ? e2 : ALPHA_S * e2;
            float e3 = s1r + sv.w; e3 = (e3 > 0.f) ? e3 : ALPHA_S * e3;
            float p0 = __expf(((av.x > 0) ? e0 : NEG_INF_S) - mr);
            float p1 = __expf(((av.y > 0) ? e1 : NEG_INF_S) - mr);
            float p2 = __expf(((av.z > 0) ? e2 : NEG_INF_S) - mr);
            float p3 = __expf(((av.w > 0) ? e3 : NEG_INF_S) - mr);
            Ps[jl + 0][pr] = p0;
            Ps[jl + 1][pr] = p1;
            Ps[jl + 2][pr] = p2;
            Ps[jl + 3][pr] = p3;
            zpart += (p0 + p1) + (p2 + p3);
        }
        __syncthreads();

        // ---- GEMM: acc += P^T tile @ H tile (f32x2 packed FMA) ----
#pragma unroll 4
        for (int k = 0; k < A_BK; k++) {
            float4 pf = *(const float4*)&Ps[k][ty * 4];
            unsigned long long pp[4];
            pp[0] = pack2(pf.x, pf.x);
            pp[1] = pack2(pf.y, pf.y);
            pp[2] = pack2(pf.z, pf.z);
            pp[3] = pack2(pf.w, pf.w);
            const ulonglong2* hp = (const ulonglong2*)&Hs[k][tx * 16];
            ulonglong2 h0 = hp[0], h1 = hp[1], h2 = hp[2], h3 = hp[3];
            unsigned long long hh[8] = {h0.x, h0.y, h1.x, h1.y, h2.x, h2.y, h3.x, h3.y};
#pragma unroll
            for (int i = 0; i < 4; i++)
#pragma unroll
                for (int j = 0; j < 8; j++)
                    asm("fma.rn.f32x2 %0, %1, %2, %0;"
                        : "+l"(acc[i][j]) : "l"(pp[i]), "l"(hh[j]));
        }
        __syncthreads();
    }

    // ---- z reduction (4 partials per row) ----
    zred[tid] = zpart;
    __syncthreads();
    if (tid < A_BM)
        zrow[tid] = (zred[tid * 4] + zred[tid * 4 + 1]) + (zred[tid * 4 + 2] + zred[tid * 4 + 3]);
    __syncthreads();

    // ---- normalize + ELU + store ----
#pragma unroll
    for (int i = 0; i < 4; i++) {
        int r = ty * 4 + i;
        float invz = 1.0f / zrow[r];
        float* orow = &out[(row0 + r) * FOUT + tx * 16];
#pragma unroll
        for (int j4 = 0; j4 < 4; j4++) {
            float v[4];
            unpack2(acc[i][j4 * 2 + 0], v[0], v[1]);
            unpack2(acc[i][j4 * 2 + 1], v[2], v[3]);
            float4 o;
            float t;
            t = v[0] * invz; o.x = (t > 0.f) ? t : expm1f(t);
            t = v[1] * invz; o.y = (t > 0.f) ? t : expm1f(t);
            t = v[2] * invz; o.z = (t > 0.f) ? t : expm1f(t);
            t = v[3] * invz; o.w = (t > 0.f) ? t : expm1f(t);
            *(float4*)&orow[j4 * 4] = o;
        }
    }
}

// ============================================================
// launch
// ============================================================
extern "C" void kernel_launch(void* const* d_in, const int* in_sizes, int n_in,
                              void* d_out, int out_size)
{
    const float* input = (const float*)d_in[0];   // [8192, 512]
    const int*   adj   = (const int*)  d_in[1];   // [8192, 8192]
    const float* W     = (const float*)d_in[2];   // [512, 256]
    const float* a     = (const float*)d_in[3];   // [512, 1]
    float* out = (float*)d_out;                   // [8192, 256]

    float *h, *s1, *s2, *m;
    cudaGetSymbolAddress((void**)&h,  g_h);
    cudaGetSymbolAddress((void**)&s1, g_s1);
    cudaGetSymbolAddress((void**)&s2, g_s2);
    cudaGetSymbolAddress((void**)&m,  g_m);

    gemm_h_kernel<<<dim3(N_NODES / G1_BM, FOUT / G1_BN), 256>>>(input, W, h);
    s_kernel<<<N_NODES / 8, 256>>>(h, a, s1, s2);
    rowmax_kernel<<<N_NODES, 256>>>(adj, s1, s2, m);
    attn_kernel<<<N_NODES / A_BM, 256>>>(adj, h, s1, s2, m, out);
}

// round 4
// speedup vs baseline: 5.0608x; 5.0608x over previous
#include <cuda_runtime.h>
#include <cstdint>

#define NN   8192
#define FIN  512
#define FOUT 256

// ---- scratch (static device memory; no allocation) ----
__device__ __align__(16) float g_h [NN * FOUT];
__device__ __align__(16) float g_s1[NN];
__device__ __align__(16) float g_s2[NN];
__device__ __align__(16) float g_dpart[2 * NN * FOUT];   // K-split partial D
__device__ __align__(16) float g_z[2 * NN];              // K-split partial z

// ============================================================
// helpers
// ============================================================
__device__ __forceinline__ uint32_t smem_u32(const void* p) {
    uint32_t a;
    asm("{ .reg .u64 t; cvta.to.shared.u64 t, %1; cvt.u32.u64 %0, t; }" : "=r"(a) : "l"(p));
    return a;
}
__device__ __forceinline__ uint32_t cvt_tf32(float f) {
    uint32_t u;
    asm("cvt.rna.tf32.f32 %0, %1;" : "=r"(u) : "f"(f));
    return u;
}

// ============================================================
// Kernel 1: h = input @ W   (8192x512 @ 512x256), fp32 SIMT.
// Epilogue stores tf32-rounded values (attention consumes them as tf32).
// ============================================================
#define G1_BM 128
#define G1_BN 128
#define G1_BK 16

__global__ __launch_bounds__(256) void gemm_h_kernel(
    const float* __restrict__ A, const float* __restrict__ B, float* __restrict__ C)
{
    __shared__ float As[G1_BK][G1_BM + 4];
    __shared__ float Bs[G1_BK][G1_BN + 4];

    const int row0 = blockIdx.x * G1_BM;
    const int col0 = blockIdx.y * G1_BN;
    const int tid = threadIdx.x;
    const int tx = tid & 15, ty = tid >> 4;

    float acc[8][8];
#pragma unroll
    for (int i = 0; i < 8; i++)
#pragma unroll
        for (int j = 0; j < 8; j++) acc[i][j] = 0.f;

    for (int k0 = 0; k0 < FIN; k0 += G1_BK) {
#pragma unroll
        for (int it = 0; it < 2; it++) {
            int i = tid + it * 256;
            int r = i >> 2;
            int c4 = i & 3;
            float4 v = *(const float4*)&A[(row0 + r) * FIN + k0 + c4 * 4];
            As[c4 * 4 + 0][r] = v.x;
            As[c4 * 4 + 1][r] = v.y;
            As[c4 * 4 + 2][r] = v.z;
            As[c4 * 4 + 3][r] = v.w;
        }
#pragma unroll
        for (int it = 0; it < 2; it++) {
            int i = tid + it * 256;
            int r = i >> 5;
            int c4 = i & 31;
            float4 v = *(const float4*)&B[(k0 + r) * FOUT + col0 + c4 * 4];
            *(float4*)&Bs[r][c4 * 4] = v;
        }
        __syncthreads();

#pragma unroll
        for (int k = 0; k < G1_BK; k++) {
            float af[8], bf[8];
#pragma unroll
            for (int i = 0; i < 8; i++) af[i] = As[k][ty * 8 + i];
#pragma unroll
            for (int j = 0; j < 8; j++) bf[j] = Bs[k][tx * 8 + j];
#pragma unroll
            for (int i = 0; i < 8; i++)
#pragma unroll
                for (int j = 0; j < 8; j++) acc[i][j] = fmaf(af[i], bf[j], acc[i][j]);
        }
        __syncthreads();
    }

#pragma unroll
    for (int i = 0; i < 8; i++) {
        int r = row0 + ty * 8 + i;
#pragma unroll
        for (int j4 = 0; j4 < 2; j4++) {
            float4 v;
            v.x = __uint_as_float(cvt_tf32(acc[i][j4 * 4 + 0]));
            v.y = __uint_as_float(cvt_tf32(acc[i][j4 * 4 + 1]));
            v.z = __uint_as_float(cvt_tf32(acc[i][j4 * 4 + 2]));
            v.w = __uint_as_float(cvt_tf32(acc[i][j4 * 4 + 3]));
            *(float4*)&C[r * FOUT + col0 + tx * 8 + j4 * 4] = v;
        }
    }
}

// ============================================================
// Kernel 2: s1[i] = h[i,:].a[:F],  s2[i] = h[i,:].a[F:]
// ============================================================
__global__ __launch_bounds__(256) void s_kernel(
    const float* __restrict__ h, const float* __restrict__ a,
    float* __restrict__ s1, float* __restrict__ s2)
{
    int row = blockIdx.x * 8 + (threadIdx.x >> 5);
    int lane = threadIdx.x & 31;
    float a1 = 0.f, a2 = 0.f;
#pragma unroll
    for (int c = lane; c < FOUT; c += 32) {
        float hv = h[row * FOUT + c];
        a1 = fmaf(hv, a[c], a1);
        a2 = fmaf(hv, a[FOUT + c], a2);
    }
#pragma unroll
    for (int o = 16; o; o >>= 1) {
        a1 += __shfl_xor_sync(0xffffffffu, a1, o);
        a2 += __shfl_xor_sync(0xffffffffu, a2, o);
    }
    if (lane == 0) { s1[row] = a1; s2[row] = a2; }
}

// ============================================================
// Kernel 3: fused attention GEMM on mma.sync tf32 (HMMA path).
//   grid = 128 CTAs: (row_tile 0..63) x (k_half 0..1), 512 threads.
//   Per CTA: D[128 x 256] += P[128 x 4096] @ H[4096 x 256] (tf32).
//   P (A fragments) computed in registers: adj LDG -> score -> exp -> tf32.
//   z accumulated from tf32-rounded P.  No max-subtraction needed:
//   scores bounded (|e| < ~20), masked entries -> exp(-9e15) = 0.
// ============================================================
#define AT_THREADS 512
#define KT 32
#define ATILES 128                  // 4096 / 32
#define HSTR 264                    // Hs row stride in floats (264 % 32 == 8)
#define HS_ELEMS (KT * HSTR)        // 8448 floats per buffer

__global__ void __launch_bounds__(AT_THREADS, 1) attn_kernel(const int* __restrict__ adj)
{
    extern __shared__ float sm[];
    float* Hs[2] = { sm, sm + HS_ELEMS };
    float* s2sm = sm + 2 * HS_ELEMS;          // 4096 floats

    const int tid = threadIdx.x, wid = tid >> 5, lane = tid & 31;
    const int q = lane >> 2, tc = lane & 3;
    const int wr = wid >> 1, wc = wid & 1;
    const int row_tile = blockIdx.x >> 1, khalf = blockIdx.x & 1;
    const int row0 = row_tile * 128, kbase = khalf * 4096;

    // stage s2 slice (4096 floats)
    {
        const float4* src = (const float4*)(g_s2 + kbase);
        float4* dst = (float4*)s2sm;
        dst[tid] = src[tid];
        dst[tid + 512] = src[tid + 512];
    }

    const int r0 = row0 + wr * 16 + q;
    const int r1 = r0 + 8;
    const float s1_0 = g_s1[r0], s1_1 = g_s1[r1];
    const int* adjr0 = adj + (size_t)r0 * NN + kbase;
    const int* adjr1 = adj + (size_t)r1 * NN + kbase;

    float acc[16][4];
#pragma unroll
    for (int nb = 0; nb < 16; nb++)
#pragma unroll
        for (int j = 0; j < 4; j++) acc[nb][j] = 0.f;
    float z0 = 0.f, z1 = 0.f;

    // ---- prefetch tile 0 ----
    {
        uint32_t dstb = smem_u32(Hs[0]);
        const float* src = g_h + (size_t)kbase * FOUT;
#pragma unroll
        for (int it = 0; it < 4; it++) {
            int i = tid + it * 512;
            int r = i >> 6, c4 = i & 63;
            uint32_t d = dstb + (uint32_t)(r * HSTR + c4 * 4) * 4u;
            const float* s = src + r * FOUT + c4 * 4;
            asm volatile("cp.async.cg.shared.global [%0], [%1], 16;" :: "r"(d), "l"(s));
        }
        asm volatile("cp.async.commit_group;");
    }

    for (int t = 0; t < ATILES; t++) {
        float* buf = Hs[t & 1];
        if (t + 1 < ATILES) {
            uint32_t dstb = smem_u32(Hs[(t + 1) & 1]);
            const float* src = g_h + (size_t)(kbase + (t + 1) * KT) * FOUT;
#pragma unroll
            for (int it = 0; it < 4; it++) {
                int i = tid + it * 512;
                int r = i >> 6, c4 = i & 63;
                uint32_t d = dstb + (uint32_t)(r * HSTR + c4 * 4) * 4u;
                const float* s = src + r * FOUT + c4 * 4;
                asm volatile("cp.async.cg.shared.global [%0], [%1], 16;" :: "r"(d), "l"(s));
            }
            asm volatile("cp.async.commit_group;");
            asm volatile("cp.async.wait_group 1;");
        } else {
            asm volatile("cp.async.wait_group 0;");
        }
        __syncthreads();

        const uint32_t* Hu = (const uint32_t*)buf;
#pragma unroll
        for (int s = 0; s < 4; s++) {
            const int kk = t * KT + s * 8 + tc;
            const float sA = s2sm[kk], sB = s2sm[kk + 4];
            const int m00 = adjr0[kk], m01 = adjr0[kk + 4];
            const int m10 = adjr1[kk], m11 = adjr1[kk + 4];
            uint32_t a0, a1, a2, a3;
            float e;
            e = s1_0 + sA; e = fmaxf(e, 0.2f * e); e = (m00 > 0) ? e : -9e15f;
            a0 = cvt_tf32(__expf(e)); z0 += __uint_as_float(a0);
            e = s1_1 + sA; e = fmaxf(e, 0.2f * e); e = (m10 > 0) ? e : -9e15f;
            a1 = cvt_tf32(__expf(e)); z1 += __uint_as_float(a1);
            e = s1_0 + sB; e = fmaxf(e, 0.2f * e); e = (m01 > 0) ? e : -9e15f;
            a2 = cvt_tf32(__expf(e)); z0 += __uint_as_float(a2);
            e = s1_1 + sB; e = fmaxf(e, 0.2f * e); e = (m11 > 0) ? e : -9e15f;
            a3 = cvt_tf32(__expf(e)); z1 += __uint_as_float(a3);

            const uint32_t* b0p = Hu + (s * 8 + tc) * HSTR + wc * 128 + q;
            const uint32_t* b1p = b0p + 4 * HSTR;
#pragma unroll
            for (int nb = 0; nb < 16; nb++) {
                uint32_t b0 = b0p[nb * 8], b1 = b1p[nb * 8];
                asm volatile(
                    "mma.sync.aligned.m16n8k8.row.col.f32.tf32.tf32.f32 "
                    "{%0,%1,%2,%3}, {%4,%5,%6,%7}, {%8,%9}, {%0,%1,%2,%3};"
                    : "+f"(acc[nb][0]), "+f"(acc[nb][1]),
                      "+f"(acc[nb][2]), "+f"(acc[nb][3])
                    : "r"(a0), "r"(a1), "r"(a2), "r"(a3), "r"(b0), "r"(b1));
            }
        }
        __syncthreads();
    }

    // ---- z: reduce within quad (lanes tc=0..3 hold partials of same rows) ----
    z0 += __shfl_xor_sync(0xffffffffu, z0, 1);
    z0 += __shfl_xor_sync(0xffffffffu, z0, 2);
    z1 += __shfl_xor_sync(0xffffffffu, z1, 1);
    z1 += __shfl_xor_sync(0xffffffffu, z1, 2);
    if (wc == 0 && tc == 0) {
        g_z[khalf * NN + r0] = z0;
        g_z[khalf * NN + r1] = z1;
    }

    // ---- store partial D ----
    float* dp = g_dpart + (size_t)khalf * NN * FOUT;
#pragma unroll
    for (int nb = 0; nb < 16; nb++) {
        int c = wc * 128 + nb * 8 + tc * 2;
        *(float2*)&dp[(size_t)r0 * FOUT + c] = make_float2(acc[nb][0], acc[nb][1]);
        *(float2*)&dp[(size_t)r1 * FOUT + c] = make_float2(acc[nb][2], acc[nb][3]);
    }
}

// ============================================================
// Kernel 4: combine K-split partials, normalize, ELU
// ============================================================
__global__ __launch_bounds__(256) void combine_kernel(float* __restrict__ out)
{
    int idx = blockIdx.x * 256 + threadIdx.x;        // float4 index
    const float4* d0 = (const float4*)g_dpart;
    const float4* d1 = d0 + (NN * FOUT / 4);
    float4 a = d0[idx], b = d1[idx];
    int row = idx >> 6;
    float inv = 1.0f / (g_z[row] + g_z[NN + row]);
    float4 o; float t;
    t = (a.x + b.x) * inv; o.x = (t > 0.f) ? t : expm1f(t);
    t = (a.y + b.y) * inv; o.y = (t > 0.f) ? t : expm1f(t);
    t = (a.z + b.z) * inv; o.z = (t > 0.f) ? t : expm1f(t);
    t = (a.w + b.w) * inv; o.w = (t > 0.f) ? t : expm1f(t);
    ((float4*)out)[idx] = o;
}

// ============================================================
// launch
// ============================================================
#define AT_SMEM ((2 * HS_ELEMS + 4096) * 4)

extern "C" void kernel_launch(void* const* d_in, const int* in_sizes, int n_in,
                              void* d_out, int out_size)
{
    const float* input = (const float*)d_in[0];   // [8192, 512]
    const int*   adj   = (const int*)  d_in[1];   // [8192, 8192]
    const float* W     = (const float*)d_in[2];   // [512, 256]
    const float* a     = (const float*)d_in[3];   // [512, 1]
    float* out = (float*)d_out;                   // [8192, 256]

    float *h, *s1, *s2;
    cudaGetSymbolAddress((void**)&h,  g_h);
    cudaGetSymbolAddress((void**)&s1, g_s1);
    cudaGetSymbolAddress((void**)&s2, g_s2);

    cudaFuncSetAttribute(attn_kernel, cudaFuncAttributeMaxDynamicSharedMemorySize, AT_SMEM);

    gemm_h_kernel<<<dim3(NN / G1_BM, FOUT / G1_BN), 256>>>(input, W, h);
    s_kernel<<<NN / 8, 256>>>(h, a, s1, s2);
    attn_kernel<<<128, AT_THREADS, AT_SMEM>>>(adj);
    combine_kernel<<<NN * FOUT / 4 / 256, 256>>>(out);
}

// round 5
// speedup vs baseline: 5.9162x; 1.1690x over previous
#include <cuda_runtime.h>
#include <cstdint>

#define NN   8192
#define FIN  512
#define FOUT 256

// ---- scratch (static device memory; no allocation) ----
__device__ __align__(16) float g_h [NN * FOUT];
__device__ __align__(16) float g_s1[NN];
__device__ __align__(16) float2 g_e1[NN];          // (exp(s1), exp(0.2 s1))
__device__ __align__(16) float4 g_e2[NN];          // (s2, exp(s2), exp(0.2 s2), 0)
__device__ __align__(16) float g_dpart[2 * NN * FOUT];   // K-split partial D
__device__ __align__(16) float g_z[2 * NN];              // K-split partial z

// ============================================================
// helpers
// ============================================================
__device__ __forceinline__ uint32_t smem_u32(const void* p) {
    uint32_t a;
    asm("{ .reg .u64 t; cvta.to.shared.u64 t, %1; cvt.u32.u64 %0, t; }" : "=r"(a) : "l"(p));
    return a;
}
__device__ __forceinline__ uint32_t cvt_tf32(float f) {
    uint32_t u;
    asm("cvt.rna.tf32.f32 %0, %1;" : "=r"(u) : "f"(f));
    return u;
}

// ============================================================
// Kernel 1: h = input @ W   (8192x512 @ 512x256), fp32 SIMT.
// Epilogue stores tf32-rounded values (attention consumes them as tf32).
// ============================================================
#define G1_BM 128
#define G1_BN 128
#define G1_BK 16

__global__ __launch_bounds__(256) void gemm_h_kernel(
    const float* __restrict__ A, const float* __restrict__ B, float* __restrict__ C)
{
    __shared__ float As[G1_BK][G1_BM + 4];
    __shared__ float Bs[G1_BK][G1_BN + 4];

    const int row0 = blockIdx.x * G1_BM;
    const int col0 = blockIdx.y * G1_BN;
    const int tid = threadIdx.x;
    const int tx = tid & 15, ty = tid >> 4;

    float acc[8][8];
#pragma unroll
    for (int i = 0; i < 8; i++)
#pragma unroll
        for (int j = 0; j < 8; j++) acc[i][j] = 0.f;

    for (int k0 = 0; k0 < FIN; k0 += G1_BK) {
#pragma unroll
        for (int it = 0; it < 2; it++) {
            int i = tid + it * 256;
            int r = i >> 2;
            int c4 = i & 3;
            float4 v = *(const float4*)&A[(row0 + r) * FIN + k0 + c4 * 4];
            As[c4 * 4 + 0][r] = v.x;
            As[c4 * 4 + 1][r] = v.y;
            As[c4 * 4 + 2][r] = v.z;
            As[c4 * 4 + 3][r] = v.w;
        }
#pragma unroll
        for (int it = 0; it < 2; it++) {
            int i = tid + it * 256;
            int r = i >> 5;
            int c4 = i & 31;
            float4 v = *(const float4*)&B[(k0 + r) * FOUT + col0 + c4 * 4];
            *(float4*)&Bs[r][c4 * 4] = v;
        }
        __syncthreads();

#pragma unroll
        for (int k = 0; k < G1_BK; k++) {
            float af[8], bf[8];
#pragma unroll
            for (int i = 0; i < 8; i++) af[i] = As[k][ty * 8 + i];
#pragma unroll
            for (int j = 0; j < 8; j++) bf[j] = Bs[k][tx * 8 + j];
#pragma unroll
            for (int i = 0; i < 8; i++)
#pragma unroll
                for (int j = 0; j < 8; j++) acc[i][j] = fmaf(af[i], bf[j], acc[i][j]);
        }
        __syncthreads();
    }

#pragma unroll
    for (int i = 0; i < 8; i++) {
        int r = row0 + ty * 8 + i;
#pragma unroll
        for (int j4 = 0; j4 < 2; j4++) {
            float4 v;
            v.x = __uint_as_float(cvt_tf32(acc[i][j4 * 4 + 0]));
            v.y = __uint_as_float(cvt_tf32(acc[i][j4 * 4 + 1]));
            v.z = __uint_as_float(cvt_tf32(acc[i][j4 * 4 + 2]));
            v.w = __uint_as_float(cvt_tf32(acc[i][j4 * 4 + 3]));
            *(float4*)&C[r * FOUT + col0 + tx * 8 + j4 * 4] = v;
        }
    }
}

// ============================================================
// Kernel 2: s1/s2 dot products + exp factor tables
// ============================================================
__global__ __launch_bounds__(256) void s_kernel(
    const float* __restrict__ h, const float* __restrict__ a)
{
    int row = blockIdx.x * 8 + (threadIdx.x >> 5);
    int lane = threadIdx.x & 31;
    float a1 = 0.f, a2 = 0.f;
#pragma unroll
    for (int c = lane; c < FOUT; c += 32) {
        float hv = h[row * FOUT + c];
        a1 = fmaf(hv, a[c], a1);
        a2 = fmaf(hv, a[FOUT + c], a2);
    }
#pragma unroll
    for (int o = 16; o; o >>= 1) {
        a1 += __shfl_xor_sync(0xffffffffu, a1, o);
        a2 += __shfl_xor_sync(0xffffffffu, a2, o);
    }
    if (lane == 0) {
        g_s1[row] = a1;
        g_e1[row] = make_float2(expf(a1), expf(0.2f * a1));
        g_e2[row] = make_float4(a2, expf(a2), expf(0.2f * a2), 0.f);
    }
}

// ============================================================
// Kernel 3: fused attention GEMM on mma.sync tf32.
//   grid = 128: 32 row-tiles (256 rows) x 2 k-half x 2 n-half.
//   8 warps/CTA, each warp: 32 rows x 128 cols (+8-col ones block -> z).
//   P in registers via factorized exp: no MUFU in hot loop.
// ============================================================
#define AT_THREADS 256
#define KT 32
#define ATILES 128                  // 4096 / 32
#define HSTR 136                    // 136 % 32 == 8 -> conflict-free B LDS
#define HS_ELEMS (KT * HSTR)        // 4352 floats per buffer

__global__ void __launch_bounds__(AT_THREADS, 1) attn_kernel(const int* __restrict__ adj)
{
    extern __shared__ float sm[];
    float* HsB[2] = { sm, sm + HS_ELEMS };
    float4* e2sm = (float4*)(sm + 2 * HS_ELEMS);     // 4096 float4

    const int tid = threadIdx.x, wid = tid >> 5, lane = tid & 31;
    const int q = lane >> 2, tc = lane & 3;
    const int rt = blockIdx.x >> 2, kh = (blockIdx.x >> 1) & 1, nh = blockIdx.x & 1;
    const int row0 = rt * 256, kbase = kh * 4096, nbase = nh * 128;

    // ---- stage e2 table (4096 float4 = 64 KB) ----
    {
        uint32_t dst = smem_u32(e2sm) + (uint32_t)tid * 16u;
        const float4* src = g_e2 + kbase + tid;
#pragma unroll
        for (int it = 0; it < 16; it++)
            asm volatile("cp.async.cg.shared.global [%0], [%1], 16;"
                         :: "r"(dst + it * 4096u), "l"(src + it * 256));
        asm volatile("cp.async.commit_group;");
    }
    // ---- ones columns (cols 128..135, both buffers) ----
    for (int i = tid; i < KT * 8; i += AT_THREADS) {
        int r = i >> 3, c = i & 7;
        HsB[0][r * HSTR + 128 + c] = 1.f;
        HsB[1][r * HSTR + 128 + c] = 1.f;
    }
    // ---- prefetch H tile 0 ----
    {
        uint32_t dstb = smem_u32(HsB[0]);
        const float* src = g_h + (size_t)kbase * FOUT + nbase;
#pragma unroll
        for (int it = 0; it < 4; it++) {
            int i = tid + it * AT_THREADS;
            int r = i >> 5, c4 = i & 31;
            asm volatile("cp.async.cg.shared.global [%0], [%1], 16;"
                         :: "r"(dstb + (uint32_t)(r * HSTR + c4 * 4) * 4u),
                            "l"(src + r * FOUT + c4 * 4));
        }
        asm volatile("cp.async.commit_group;");
    }

    // ---- per-row constants (4 rows per lane: q + {0,8,16,24}) ----
    float negs1[4], e1p[4], e1n[4];
    const int* ar[4];
#pragma unroll
    for (int r = 0; r < 4; r++) {
        int grow = row0 + wid * 32 + q + r * 8;
        negs1[r] = -g_s1[grow];
        float2 e = g_e1[grow];
        e1p[r] = e.x; e1n[r] = e.y;
        ar[r] = adj + (size_t)grow * NN + kbase;
    }

    float acc[2][17][4];
#pragma unroll
    for (int g = 0; g < 2; g++)
#pragma unroll
        for (int nb = 0; nb < 17; nb++)
#pragma unroll
            for (int j = 0; j < 4; j++) acc[g][nb][j] = 0.f;

    for (int t = 0; t < ATILES; t++) {
        if (t + 1 < ATILES) {
            uint32_t dstb = smem_u32(HsB[(t + 1) & 1]);
            const float* src = g_h + (size_t)(kbase + (t + 1) * KT) * FOUT + nbase;
#pragma unroll
            for (int it = 0; it < 4; it++) {
                int i = tid + it * AT_THREADS;
                int r = i >> 5, c4 = i & 31;
                asm volatile("cp.async.cg.shared.global [%0], [%1], 16;"
                             :: "r"(dstb + (uint32_t)(r * HSTR + c4 * 4) * 4u),
                                "l"(src + r * FOUT + c4 * 4));
            }
            asm volatile("cp.async.commit_group;");
            asm volatile("cp.async.wait_group 1;");
        } else {
            asm volatile("cp.async.wait_group 0;");
        }
        __syncthreads();

        const uint32_t* Hu = (const uint32_t*)HsB[t & 1];

#pragma unroll
        for (int s = 0; s < 4; s++) {
            const int kl = t * KT + s * 8 + tc;        // local j index
            float4 eA = e2sm[kl];
            float4 eB = e2sm[kl + 4];
            int mA[4], mB[4];
#pragma unroll
            for (int r = 0; r < 4; r++) { mA[r] = ar[r][kl]; mB[r] = ar[r][kl + 4]; }

            uint32_t ag0[4], ag1[4];
#pragma unroll
            for (int r = 0; r < 4; r++) {
                bool sA = eA.x > negs1[r];
                float pA = (sA ? e1p[r] : e1n[r]) * (sA ? eA.y : eA.z);
                pA = (mA[r] > 0) ? pA : 0.f;
                bool sB = eB.x > negs1[r];
                float pB = (sB ? e1p[r] : e1n[r]) * (sB ? eB.y : eB.z);
                pB = (mB[r] > 0) ? pB : 0.f;
                uint32_t* dst = (r < 2) ? ag0 : ag1;
                int pos = r & 1;
                dst[pos]     = __float_as_uint(pA);    // rows q, q+8 @ kA
                dst[2 + pos] = __float_as_uint(pB);    // rows q, q+8 @ kB
            }

            const uint32_t* bp = Hu + (s * 8 + tc) * HSTR + q;
#pragma unroll
            for (int nb = 0; nb < 17; nb++) {
                uint32_t b0 = bp[nb * 8];
                uint32_t b1 = bp[nb * 8 + 4 * HSTR];
                asm volatile(
                    "mma.sync.aligned.m16n8k8.row.col.f32.tf32.tf32.f32 "
                    "{%0,%1,%2,%3}, {%4,%5,%6,%7}, {%8,%9}, {%0,%1,%2,%3};"
                    : "+f"(acc[0][nb][0]), "+f"(acc[0][nb][1]),
                      "+f"(acc[0][nb][2]), "+f"(acc[0][nb][3])
                    : "r"(ag0[0]), "r"(ag0[1]), "r"(ag0[2]), "r"(ag0[3]),
                      "r"(b0), "r"(b1));
                asm volatile(
                    "mma.sync.aligned.m16n8k8.row.col.f32.tf32.tf32.f32 "
                    "{%0,%1,%2,%3}, {%4,%5,%6,%7}, {%8,%9}, {%0,%1,%2,%3};"
                    : "+f"(acc[1][nb][0]), "+f"(acc[1][nb][1]),
                      "+f"(acc[1][nb][2]), "+f"(acc[1][nb][3])
                    : "r"(ag1[0]), "r"(ag1[1]), "r"(ag1[2]), "r"(ag1[3]),
                      "r"(b0), "r"(b1));
            }
        }
        __syncthreads();
    }

    // ---- store partial D + z ----
    float* dp = g_dpart + (size_t)kh * NN * FOUT;
#pragma unroll
    for (int g = 0; g < 2; g++) {
        const int rlo = row0 + wid * 32 + g * 16 + q;
        const int rhi = rlo + 8;
#pragma unroll
        for (int nb = 0; nb < 16; nb++) {
            int c = nbase + nb * 8 + tc * 2;
            *(float2*)&dp[(size_t)rlo * FOUT + c] = make_float2(acc[g][nb][0], acc[g][nb][1]);
            *(float2*)&dp[(size_t)rhi * FOUT + c] = make_float2(acc[g][nb][2], acc[g][nb][3]);
        }
        if (nh == 0 && tc == 0) {
            g_z[kh * NN + rlo] = acc[g][16][0];
            g_z[kh * NN + rhi] = acc[g][16][2];
        }
    }
}

// ============================================================
// Kernel 4: combine K-split partials, normalize, ELU
// ============================================================
__global__ __launch_bounds__(256) void combine_kernel(float* __restrict__ out)
{
    int idx = blockIdx.x * 256 + threadIdx.x;        // float4 index
    const float4* d0 = (const float4*)g_dpart;
    const float4* d1 = d0 + (NN * FOUT / 4);
    float4 a = d0[idx], b = d1[idx];
    int row = idx >> 6;
    float inv = 1.0f / (g_z[row] + g_z[NN + row]);
    float4 o; float t;
    t = (a.x + b.x) * inv; o.x = (t > 0.f) ? t : expm1f(t);
    t = (a.y + b.y) * inv; o.y = (t > 0.f) ? t : expm1f(t);
    t = (a.z + b.z) * inv; o.z = (t > 0.f) ? t : expm1f(t);
    t = (a.w + b.w) * inv; o.w = (t > 0.f) ? t : expm1f(t);
    ((float4*)out)[idx] = o;
}

// ============================================================
// launch
// ============================================================
#define AT_SMEM (2 * HS_ELEMS * 4 + 4096 * 16)

extern "C" void kernel_launch(void* const* d_in, const int* in_sizes, int n_in,
                              void* d_out, int out_size)
{
    const float* input = (const float*)d_in[0];   // [8192, 512]
    const int*   adj   = (const int*)  d_in[1];   // [8192, 8192]
    const float* W     = (const float*)d_in[2];   // [512, 256]
    const float* a     = (const float*)d_in[3];   // [512, 1]
    float* out = (float*)d_out;                   // [8192, 256]

    float* h;
    cudaGetSymbolAddress((void**)&h, g_h);

    cudaFuncSetAttribute(attn_kernel, cudaFuncAttributeMaxDynamicSharedMemorySize, AT_SMEM);

    gemm_h_kernel<<<dim3(NN / G1_BM, FOUT / G1_BN), 256>>>(input, W, h);
    s_kernel<<<NN / 8, 256>>>(h, a);
    attn_kernel<<<128, AT_THREADS, AT_SMEM>>>(adj);
    combine_kernel<<<NN * FOUT / 4 / 256, 256>>>(out);
}

// round 6
// speedup vs baseline: 7.2375x; 1.2233x over previous
#include <cuda_runtime.h>
#include <cstdint>

#define NN   8192
#define FIN  512
#define FOUT 256

// ---- scratch (static device memory; no allocation) ----
__device__ __align__(16) float g_h [NN * FOUT];
__device__ __align__(16) float2 g_e1[NN];            // (exp(s1), exp(0.2 s1))
__device__ __align__(16) float2 g_e2[NN];            // (exp(s2), exp(0.2 s2))
__device__ __align__(16) uint32_t g_mask[NN * 256];  // bit-packed adj, [row][tile32]
__device__ __align__(16) float g_dpart[2 * NN * FOUT];
__device__ __align__(16) float g_z[2 * NN];

// ============================================================
// helpers
// ============================================================
__device__ __forceinline__ uint32_t smem_u32(const void* p) {
    uint32_t a;
    asm("{ .reg .u64 t; cvta.to.shared.u64 t, %1; cvt.u32.u64 %0, t; }" : "=r"(a) : "l"(p));
    return a;
}
__device__ __forceinline__ uint32_t cvt_tf32(float f) {
    uint32_t u;
    asm("cvt.rna.tf32.f32 %0, %1;" : "=r"(u) : "f"(f));
    return u;
}
__device__ __forceinline__ unsigned long long pack2(float lo, float hi) {
    unsigned long long r;
    asm("mov.b64 %0, {%1, %2};" : "=l"(r) : "f"(lo), "f"(hi));
    return r;
}
__device__ __forceinline__ void unpack2(unsigned long long v, float& lo, float& hi) {
    asm("mov.b64 {%0, %1}, %2;" : "=f"(lo), "=f"(hi) : "l"(v));
}

// ============================================================
// Kernel 0: bit-pack adjacency.  mask[row][t] bit j = adj[row][t*32+j] > 0
// ============================================================
__global__ __launch_bounds__(256) void pack_kernel(const int* __restrict__ adj,
                                                   uint32_t* __restrict__ mask)
{
    const int row = blockIdx.x;
    const int wid = threadIdx.x >> 5, lane = threadIdx.x & 31;
    const int* ar = adj + (size_t)row * NN;
#pragma unroll 4
    for (int i = 0; i < 32; i++) {
        int t = wid * 32 + i;
        int v = ar[t * 32 + lane];
        uint32_t b = __ballot_sync(0xffffffffu, v > 0);
        if (lane == 0) mask[row * 256 + t] = b;
    }
}

// ============================================================
// Kernel 1: h = input @ W, fp32 via packed fma.rn.f32x2.
// Epilogue stores tf32-rounded h.
// ============================================================
#define G1_BM 128
#define G1_BN 128
#define G1_BK 16

__global__ __launch_bounds__(256) void gemm_h_kernel(
    const float* __restrict__ A, const float* __restrict__ B, float* __restrict__ C)
{
    __shared__ float As[G1_BK][G1_BM + 4];
    __shared__ float Bs[G1_BK][G1_BN + 4];

    const int row0 = blockIdx.x * G1_BM;
    const int col0 = blockIdx.y * G1_BN;
    const int tid = threadIdx.x;
    const int tx = tid & 15, ty = tid >> 4;

    unsigned long long acc2[8][4];
#pragma unroll
    for (int i = 0; i < 8; i++)
#pragma unroll
        for (int j = 0; j < 4; j++) acc2[i][j] = 0ULL;

    for (int k0 = 0; k0 < FIN; k0 += G1_BK) {
#pragma unroll
        for (int it = 0; it < 2; it++) {
            int i = tid + it * 256;
            int r = i >> 2;
            int c4 = i & 3;
            float4 v = *(const float4*)&A[(row0 + r) * FIN + k0 + c4 * 4];
            As[c4 * 4 + 0][r] = v.x;
            As[c4 * 4 + 1][r] = v.y;
            As[c4 * 4 + 2][r] = v.z;
            As[c4 * 4 + 3][r] = v.w;
        }
#pragma unroll
        for (int it = 0; it < 2; it++) {
            int i = tid + it * 256;
            int r = i >> 5;
            int c4 = i & 31;
            float4 v = *(const float4*)&B[(k0 + r) * FOUT + col0 + c4 * 4];
            *(float4*)&Bs[r][c4 * 4] = v;
        }
        __syncthreads();

#pragma unroll
        for (int k = 0; k < G1_BK; k++) {
            float4 a0 = *(const float4*)&As[k][ty * 8];
            float4 a1 = *(const float4*)&As[k][ty * 8 + 4];
            float af[8] = {a0.x, a0.y, a0.z, a0.w, a1.x, a1.y, a1.z, a1.w};
            ulonglong2 b01 = ((const ulonglong2*)&Bs[k][tx * 8])[0];
            ulonglong2 b23 = ((const ulonglong2*)&Bs[k][tx * 8])[1];
            unsigned long long bb[4] = {b01.x, b01.y, b23.x, b23.y};
#pragma unroll
            for (int i = 0; i < 8; i++) {
                unsigned long long pa = pack2(af[i], af[i]);
#pragma unroll
                for (int j = 0; j < 4; j++)
                    asm("fma.rn.f32x2 %0, %1, %2, %0;"
                        : "+l"(acc2[i][j]) : "l"(pa), "l"(bb[j]));
            }
        }
        __syncthreads();
    }

#pragma unroll
    for (int i = 0; i < 8; i++) {
        int r = row0 + ty * 8 + i;
#pragma unroll
        for (int j4 = 0; j4 < 2; j4++) {
            float v0, v1, v2, v3;
            unpack2(acc2[i][j4 * 2 + 0], v0, v1);
            unpack2(acc2[i][j4 * 2 + 1], v2, v3);
            float4 v;
            v.x = __uint_as_float(cvt_tf32(v0));
            v.y = __uint_as_float(cvt_tf32(v1));
            v.z = __uint_as_float(cvt_tf32(v2));
            v.w = __uint_as_float(cvt_tf32(v3));
            *(float4*)&C[r * FOUT + col0 + tx * 8 + j4 * 4] = v;
        }
    }
}

// ============================================================
// Kernel 2: s1/s2 dot products -> exp factor tables
// ============================================================
__global__ __launch_bounds__(256) void s_kernel(
    const float* __restrict__ h, const float* __restrict__ a)
{
    int row = blockIdx.x * 8 + (threadIdx.x >> 5);
    int lane = threadIdx.x & 31;
    float a1 = 0.f, a2 = 0.f;
#pragma unroll
    for (int c = lane; c < FOUT; c += 32) {
        float hv = h[row * FOUT + c];
        a1 = fmaf(hv, a[c], a1);
        a2 = fmaf(hv, a[FOUT + c], a2);
    }
#pragma unroll
    for (int o = 16; o; o >>= 1) {
        a1 += __shfl_xor_sync(0xffffffffu, a1, o);
        a2 += __shfl_xor_sync(0xffffffffu, a2, o);
    }
    if (lane == 0) {
        g_e1[row] = make_float2(expf(a1), expf(0.2f * a1));
        g_e2[row] = make_float2(expf(a2), expf(0.2f * a2));
    }
}

// ============================================================
// Kernel 3: fused attention GEMM on mma.sync tf32.
//   grid 128 = 32 rowtiles(256) x 2 khalf x 2 nhalf.  256 threads.
//   P = mask ? max(e1p*e2p, e1n*e2n) : 0   (exp-factorized LeakyReLU)
//   masks from bit-packed table (register-prefetched, L2-resident).
//   z via ones-column (17th n-block) of the MMA.
// ============================================================
#define AT_THREADS 256
#define KT 32
#define ATILES 128
#define HSTR 136                    // 136 % 32 == 8 -> conflict-free B LDS
#define HS_ELEMS (KT * HSTR)

__global__ void __launch_bounds__(AT_THREADS, 1) attn_kernel(void)
{
    extern __shared__ float sm[];
    float* HsB[2] = { sm, sm + HS_ELEMS };
    float2* e2sm = (float2*)(sm + 2 * HS_ELEMS);     // 4096 float2 = 32 KB

    const int tid = threadIdx.x, wid = tid >> 5, lane = tid & 31;
    const int q = lane >> 2, tc = lane & 3;
    const int rt = blockIdx.x >> 2, kh = (blockIdx.x >> 1) & 1, nh = blockIdx.x & 1;
    const int row0 = rt * 256, kbase = kh * 4096, nbase = nh * 128;

    // ---- stage e2 table (4096 float2 = 32 KB) ----
    {
        uint32_t dst = smem_u32(e2sm) + (uint32_t)tid * 16u;
        const float4* src = (const float4*)(g_e2 + kbase) + tid;
#pragma unroll
        for (int it = 0; it < 8; it++)
            asm volatile("cp.async.cg.shared.global [%0], [%1], 16;"
                         :: "r"(dst + it * 4096u), "l"(src + it * 256));
        asm volatile("cp.async.commit_group;");
    }
    // ---- ones columns (cols 128..135, both buffers) ----
    for (int i = tid; i < KT * 8; i += AT_THREADS) {
        int r = i >> 3, c = i & 7;
        HsB[0][r * HSTR + 128 + c] = 1.f;
        HsB[1][r * HSTR + 128 + c] = 1.f;
    }
    // ---- prefetch H tile 0 ----
    {
        uint32_t dstb = smem_u32(HsB[0]);
        const float* src = g_h + (size_t)kbase * FOUT + nbase;
#pragma unroll
        for (int it = 0; it < 4; it++) {
            int i = tid + it * AT_THREADS;
            int r = i >> 5, c4 = i & 31;
            asm volatile("cp.async.cg.shared.global [%0], [%1], 16;"
                         :: "r"(dstb + (uint32_t)(r * HSTR + c4 * 4) * 4u),
                            "l"(src + r * FOUT + c4 * 4));
        }
        asm volatile("cp.async.commit_group;");
    }

    // ---- per-row constants (rows q + {0,8,16,24} of warp's 32) ----
    float e1p[4], e1n[4];
    const uint32_t* mrow[4];
#pragma unroll
    for (int r = 0; r < 4; r++) {
        int grow = row0 + wid * 32 + q + r * 8;
        float2 e = g_e1[grow];
        e1p[r] = e.x; e1n[r] = e.y;
        mrow[r] = g_mask + (size_t)grow * 256 + kh * 128;
    }
    uint32_t mcur[4];
#pragma unroll
    for (int r = 0; r < 4; r++) mcur[r] = mrow[r][0];

    float acc[2][17][4];
#pragma unroll
    for (int g = 0; g < 2; g++)
#pragma unroll
        for (int nb = 0; nb < 17; nb++)
#pragma unroll
            for (int j = 0; j < 4; j++) acc[g][nb][j] = 0.f;

    for (int t = 0; t < ATILES; t++) {
        if (t + 1 < ATILES) {
            uint32_t dstb = smem_u32(HsB[(t + 1) & 1]);
            const float* src = g_h + (size_t)(kbase + (t + 1) * KT) * FOUT + nbase;
#pragma unroll
            for (int it = 0; it < 4; it++) {
                int i = tid + it * AT_THREADS;
                int r = i >> 5, c4 = i & 31;
                asm volatile("cp.async.cg.shared.global [%0], [%1], 16;"
                             :: "r"(dstb + (uint32_t)(r * HSTR + c4 * 4) * 4u),
                                "l"(src + r * FOUT + c4 * 4));
            }
            asm volatile("cp.async.commit_group;");
            asm volatile("cp.async.wait_group 1;");
        } else {
            asm volatile("cp.async.wait_group 0;");
        }
        __syncthreads();

        // prefetch next tile's mask words
        uint32_t mnext[4] = {0, 0, 0, 0};
        if (t + 1 < ATILES) {
#pragma unroll
            for (int r = 0; r < 4; r++) mnext[r] = mrow[r][t + 1];
        }

        const uint32_t* Hu = (const uint32_t*)HsB[t & 1];

#pragma unroll
        for (int s = 0; s < 4; s++) {
            const int kl = t * KT + s * 8 + tc;
            float2 eA = e2sm[kl];
            float2 eB = e2sm[kl + 4];

            uint32_t ag0[4], ag1[4];
#pragma unroll
            for (int r = 0; r < 4; r++) {
                float pA = fmaxf(e1p[r] * eA.x, e1n[r] * eA.y);
                pA = ((mcur[r] >> (s * 8 + tc)) & 1u) ? pA : 0.f;
                float pB = fmaxf(e1p[r] * eB.x, e1n[r] * eB.y);
                pB = ((mcur[r] >> (s * 8 + tc + 4)) & 1u) ? pB : 0.f;
                uint32_t* dst = (r < 2) ? ag0 : ag1;
                int pos = r & 1;
                dst[pos]     = __float_as_uint(pA);
                dst[2 + pos] = __float_as_uint(pB);
            }

            const uint32_t* bp = Hu + (s * 8 + tc) * HSTR + q;
#pragma unroll
            for (int nb = 0; nb < 17; nb++) {
                uint32_t b0 = bp[nb * 8];
                uint32_t b1 = bp[nb * 8 + 4 * HSTR];
                asm volatile(
                    "mma.sync.aligned.m16n8k8.row.col.f32.tf32.tf32.f32 "
                    "{%0,%1,%2,%3}, {%4,%5,%6,%7}, {%8,%9}, {%0,%1,%2,%3};"
                    : "+f"(acc[0][nb][0]), "+f"(acc[0][nb][1]),
                      "+f"(acc[0][nb][2]), "+f"(acc[0][nb][3])
                    : "r"(ag0[0]), "r"(ag0[1]), "r"(ag0[2]), "r"(ag0[3]),
                      "r"(b0), "r"(b1));
                asm volatile(
                    "mma.sync.aligned.m16n8k8.row.col.f32.tf32.tf32.f32 "
                    "{%0,%1,%2,%3}, {%4,%5,%6,%7}, {%8,%9}, {%0,%1,%2,%3};"
                    : "+f"(acc[1][nb][0]), "+f"(acc[1][nb][1]),
                      "+f"(acc[1][nb][2]), "+f"(acc[1][nb][3])
                    : "r"(ag1[0]), "r"(ag1[1]), "r"(ag1[2]), "r"(ag1[3]),
                      "r"(b0), "r"(b1));
            }
        }
        __syncthreads();

#pragma unroll
        for (int r = 0; r < 4; r++) mcur[r] = mnext[r];
    }

    // ---- store partial D + z ----
    float* dp = g_dpart + (size_t)kh * NN * FOUT;
#pragma unroll
    for (int g = 0; g < 2; g++) {
        const int rlo = row0 + wid * 32 + g * 16 + q;
        const int rhi = rlo + 8;
#pragma unroll
        for (int nb = 0; nb < 16; nb++) {
            int c = nbase + nb * 8 + tc * 2;
            *(float2*)&dp[(size_t)rlo * FOUT + c] = make_float2(acc[g][nb][0], acc[g][nb][1]);
            *(float2*)&dp[(size_t)rhi * FOUT + c] = make_float2(acc[g][nb][2], acc[g][nb][3]);
        }
        if (nh == 0 && tc == 0) {
            g_z[kh * NN + rlo] = acc[g][16][0];
            g_z[kh * NN + rhi] = acc[g][16][2];
        }
    }
}

// ============================================================
// Kernel 4: combine K-split partials, normalize, ELU
// ============================================================
__global__ __launch_bounds__(256) void combine_kernel(float* __restrict__ out)
{
    int idx = blockIdx.x * 256 + threadIdx.x;
    const float4* d0 = (const float4*)g_dpart;
    const float4* d1 = d0 + (NN * FOUT / 4);
    float4 a = d0[idx], b = d1[idx];
    int row = idx >> 6;
    float inv = 1.0f / (g_z[row] + g_z[NN + row]);
    float4 o; float t;
    t = (a.x + b.x) * inv; o.x = (t > 0.f) ? t : expm1f(t);
    t = (a.y + b.y) * inv; o.y = (t > 0.f) ? t : expm1f(t);
    t = (a.z + b.z) * inv; o.z = (t > 0.f) ? t : expm1f(t);
    t = (a.w + b.w) * inv; o.w = (t > 0.f) ? t : expm1f(t);
    ((float4*)out)[idx] = o;
}

// ============================================================
// launch
// ============================================================
#define AT_SMEM (2 * HS_ELEMS * 4 + 4096 * 8)

extern "C" void kernel_launch(void* const* d_in, const int* in_sizes, int n_in,
                              void* d_out, int out_size)
{
    const float* input = (const float*)d_in[0];   // [8192, 512]
    const int*   adj   = (const int*)  d_in[1];   // [8192, 8192]
    const float* W     = (const float*)d_in[2];   // [512, 256]
    const float* a     = (const float*)d_in[3];   // [512, 1]
    float* out = (float*)d_out;                   // [8192, 256]

    float* h;
    uint32_t* mask;
    cudaGetSymbolAddress((void**)&h, g_h);
    cudaGetSymbolAddress((void**)&mask, g_mask);

    cudaFuncSetAttribute(attn_kernel, cudaFuncAttributeMaxDynamicSharedMemorySize, AT_SMEM);

    gemm_h_kernel<<<dim3(NN / G1_BM, FOUT / G1_BN), 256>>>(input, W, h);
    s_kernel<<<NN / 8, 256>>>(h, a);
    pack_kernel<<<NN, 256>>>(adj, mask);
    attn_kernel<<<128, AT_THREADS, AT_SMEM>>>();
    combine_kernel<<<NN * FOUT / 4 / 256, 256>>>(out);
}

// round 8
// speedup vs baseline: 8.8126x; 1.2176x over previous
#include <cuda_runtime.h>
#include <cuda_fp16.h>
#include <cstdint>

#define NN   8192
#define FIN  512
#define FOUT 256

// ---- scratch (static device memory; no allocation) ----
__device__ __align__(16) float g_h [NN * FOUT];          // fp32 h
__device__ __align__(16) __half g_hT[FOUT * NN];         // fp16 h transposed [n][j]
__device__ __align__(16) float g_s1r[NN];
__device__ __align__(16) float g_s2r[NN];
__device__ __align__(16) float2 g_e1[NN];                // (exp(s1-m), exp(.2 s1-m))
__device__ __align__(16) float2 g_e2[NN];                // (exp(s2), exp(.2 s2))
__device__ __align__(16) uint32_t g_mask[NN * 256];      // bit-packed adj
__device__ __align__(16) float g_dpart[2 * NN * FOUT];
__device__ __align__(16) float g_z[2 * NN];

// ============================================================
// helpers
// ============================================================
__device__ __forceinline__ uint32_t smem_u32(const void* p) {
    uint32_t a;
    asm("{ .reg .u64 t; cvta.to.shared.u64 t, %1; cvt.u32.u64 %0, t; }" : "=r"(a) : "l"(p));
    return a;
}
__device__ __forceinline__ unsigned long long pack2(float lo, float hi) {
    unsigned long long r;
    asm("mov.b64 %0, {%1, %2};" : "=l"(r) : "f"(lo), "f"(hi));
    return r;
}
__device__ __forceinline__ void unpack2(unsigned long long v, float& lo, float& hi) {
    asm("mov.b64 {%0, %1}, %2;" : "=f"(lo), "=f"(hi) : "l"(v));
}
__device__ __forceinline__ uint32_t f16x2_pack(float hi, float lo) {
    uint32_t r;
    asm("cvt.rn.f16x2.f32 %0, %1, %2;" : "=r"(r) : "f"(hi), "f"(lo));
    return r;
}

// ============================================================
// Kernel 0: bit-pack adjacency
// ============================================================
__global__ __launch_bounds__(256) void pack_kernel(const int* __restrict__ adj,
                                                   uint32_t* __restrict__ mask)
{
    const int row = blockIdx.x;
    const int wid = threadIdx.x >> 5, lane = threadIdx.x & 31;
    const int* ar = adj + (size_t)row * NN;
#pragma unroll 4
    for (int i = 0; i < 32; i++) {
        int t = wid * 32 + i;
        int v = ar[t * 32 + lane];
        uint32_t b = __ballot_sync(0xffffffffu, v > 0);
        if (lane == 0) mask[row * 256 + t] = b;
    }
}

// ============================================================
// Kernel 1: h = input @ W, fp32 via packed fma.rn.f32x2
// ============================================================
#define G1_BM 128
#define G1_BN 128
#define G1_BK 16

__global__ __launch_bounds__(256) void gemm_h_kernel(
    const float* __restrict__ A, const float* __restrict__ B, float* __restrict__ C)
{
    __shared__ float As[G1_BK][G1_BM + 4];
    __shared__ float Bs[G1_BK][G1_BN + 4];

    const int row0 = blockIdx.x * G1_BM;
    const int col0 = blockIdx.y * G1_BN;
    const int tid = threadIdx.x;
    const int tx = tid & 15, ty = tid >> 4;

    unsigned long long acc2[8][4];
#pragma unroll
    for (int i = 0; i < 8; i++)
#pragma unroll
        for (int j = 0; j < 4; j++) acc2[i][j] = 0ULL;

    for (int k0 = 0; k0 < FIN; k0 += G1_BK) {
#pragma unroll
        for (int it = 0; it < 2; it++) {
            int i = tid + it * 256;
            int r = i >> 2, c4 = i & 3;
            float4 v = *(const float4*)&A[(row0 + r) * FIN + k0 + c4 * 4];
            As[c4 * 4 + 0][r] = v.x;
            As[c4 * 4 + 1][r] = v.y;
            As[c4 * 4 + 2][r] = v.z;
            As[c4 * 4 + 3][r] = v.w;
        }
#pragma unroll
        for (int it = 0; it < 2; it++) {
            int i = tid + it * 256;
            int r = i >> 5, c4 = i & 31;
            float4 v = *(const float4*)&B[(k0 + r) * FOUT + col0 + c4 * 4];
            *(float4*)&Bs[r][c4 * 4] = v;
        }
        __syncthreads();

#pragma unroll
        for (int k = 0; k < G1_BK; k++) {
            float4 a0 = *(const float4*)&As[k][ty * 8];
            float4 a1 = *(const float4*)&As[k][ty * 8 + 4];
            float af[8] = {a0.x, a0.y, a0.z, a0.w, a1.x, a1.y, a1.z, a1.w};
            ulonglong2 b01 = ((const ulonglong2*)&Bs[k][tx * 8])[0];
            ulonglong2 b23 = ((const ulonglong2*)&Bs[k][tx * 8])[1];
            unsigned long long bb[4] = {b01.x, b01.y, b23.x, b23.y};
#pragma unroll
            for (int i = 0; i < 8; i++) {
                unsigned long long pa = pack2(af[i], af[i]);
#pragma unroll
                for (int j = 0; j < 4; j++)
                    asm("fma.rn.f32x2 %0, %1, %2, %0;"
                        : "+l"(acc2[i][j]) : "l"(pa), "l"(bb[j]));
            }
        }
        __syncthreads();
    }

#pragma unroll
    for (int i = 0; i < 8; i++) {
        int r = row0 + ty * 8 + i;
#pragma unroll
        for (int j4 = 0; j4 < 2; j4++) {
            float v0, v1, v2, v3;
            unpack2(acc2[i][j4 * 2 + 0], v0, v1);
            unpack2(acc2[i][j4 * 2 + 1], v2, v3);
            *(float4*)&C[r * FOUT + col0 + tx * 8 + j4 * 4] = make_float4(v0, v1, v2, v3);
        }
    }
}

// ============================================================
// Kernel 1b: transpose+convert h fp32 [NN][FOUT] -> hT fp16 [FOUT][NN]
// ============================================================
__global__ __launch_bounds__(256) void t_kernel(const float* __restrict__ h,
                                                __half* __restrict__ hT)
{
    __shared__ __half tile[32][33];
    const int r0 = blockIdx.x * 32, c0 = blockIdx.y * 32;
    const int lane = threadIdx.x & 31, w = threadIdx.x >> 5;
#pragma unroll
    for (int ii = 0; ii < 4; ii++) {
        int r = w * 4 + ii;
        tile[r][lane] = __float2half(h[(size_t)(r0 + r) * FOUT + c0 + lane]);
    }
    __syncthreads();
#pragma unroll
    for (int ii = 0; ii < 4; ii++) {
        int c = w * 4 + ii;
        hT[(size_t)(c0 + c) * NN + r0 + lane] = tile[lane][c];
    }
}

// ============================================================
// Kernel 2: s1/s2 dot products (raw)
// ============================================================
__global__ __launch_bounds__(256) void s_kernel(
    const float* __restrict__ h, const float* __restrict__ a)
{
    int row = blockIdx.x * 8 + (threadIdx.x >> 5);
    int lane = threadIdx.x & 31;
    float a1 = 0.f, a2 = 0.f;
#pragma unroll
    for (int c = lane; c < FOUT; c += 32) {
        float hv = h[row * FOUT + c];
        a1 = fmaf(hv, a[c], a1);
        a2 = fmaf(hv, a[FOUT + c], a2);
    }
#pragma unroll
    for (int o = 16; o; o >>= 1) {
        a1 += __shfl_xor_sync(0xffffffffu, a1, o);
        a2 += __shfl_xor_sync(0xffffffffu, a2, o);
    }
    if (lane == 0) { g_s1r[row] = a1; g_s2r[row] = a2; }
}

// ============================================================
// Kernel 2b: S2MAX reduction + factor tables (1 block)
//   m_r = lrelu(s1_r + S2MAX) >= score_rj  ->  P = exp(score-m) in (0,1]
// ============================================================
__global__ __launch_bounds__(256) void prep_kernel(void)
{
    __shared__ float red[256];
    float mx = -3.0e38f;
    for (int i = threadIdx.x; i < NN; i += 256) mx = fmaxf(mx, g_s2r[i]);
    red[threadIdx.x] = mx;
    __syncthreads();
#pragma unroll
    for (int s = 128; s; s >>= 1) {
        if (threadIdx.x < s) red[threadIdx.x] = fmaxf(red[threadIdx.x], red[threadIdx.x + s]);
        __syncthreads();
    }
    const float S2MAX = red[0];
    for (int r = threadIdx.x; r < NN; r += 256) {
        float s1 = g_s1r[r], s2 = g_s2r[r];
        float x = s1 + S2MAX;
        float m = fmaxf(x, 0.2f * x);
        g_e1[r] = make_float2(expf(s1 - m), expf(0.2f * s1 - m));
        g_e2[r] = make_float2(expf(s2), expf(0.2f * s2));
    }
}

// ============================================================
// Kernel 3: fused attention GEMM on mma.sync fp16 m16n8k16.
//   grid 128 = 32 rowtiles(256) x 2 kh x 2 nh.  256 threads.
//   P = mask ? max(f1p*e2p, f1n*e2n) : 0, in (0,1] -> fp16 safe.
//   H staged as fp16 H^T tiles [n][k], row stride 40 halves (conflict-free).
//   z via ones-rows (n=128..135) of B tile.
// ============================================================
#define AT_THREADS 256
#define KT 32
#define ATILES 128
#define HSTRH 40                         // halves per Hs row (40%32==8 pattern)
#define HS_BYTES (136 * HSTRH * 2)       // 10880
#define OFF_HS0 0
#define OFF_HS1 HS_BYTES
#define OFF_E2  (2 * HS_BYTES)           // 21760, 16B aligned
#define AT_SMEM (OFF_E2 + 4096 * 8)      // + e2 table 32KB

__global__ void __launch_bounds__(AT_THREADS, 1) attn_kernel(void)
{
    extern __shared__ char dsm[];
    __half* HsB[2] = { (__half*)(dsm + OFF_HS0), (__half*)(dsm + OFF_HS1) };
    float2* e2sm = (float2*)(dsm + OFF_E2);

    const int tid = threadIdx.x, wid = tid >> 5, lane = tid & 31;
    const int q = lane >> 2, tc = lane & 3;
    const int rt = blockIdx.x >> 2, kh = (blockIdx.x >> 1) & 1, nh = blockIdx.x & 1;
    const int row0 = rt * 256, kbase = kh * 4096, nbase = nh * 128;

    // ---- stage e2 table (32 KB) ----
    {
        uint32_t dst = smem_u32(e2sm) + (uint32_t)tid * 16u;
        const float4* src = (const float4*)(g_e2 + kbase) + tid;
#pragma unroll
        for (int it = 0; it < 8; it++)
            asm volatile("cp.async.cg.shared.global [%0], [%1], 16;"
                         :: "r"(dst + it * 4096u), "l"(src + it * 256));
        asm volatile("cp.async.commit_group;");
    }
    // ---- ones rows (n local 128..135), both buffers ----
    for (int i = tid; i < 8 * HSTRH / 2; i += AT_THREADS) {
        int r = 128 + i / (HSTRH / 2), c = i % (HSTRH / 2);
        ((uint32_t*)HsB[0])[(r * HSTRH) / 2 + c] = 0x3C003C00u;
        ((uint32_t*)HsB[1])[(r * HSTRH) / 2 + c] = 0x3C003C00u;
    }
    // ---- prefetch H tile 0: 128 rows x 32 halves (64B) ----
    {
        uint32_t dstb = smem_u32(HsB[0]);
        const __half* src = g_hT + (size_t)nbase * NN + kbase;
#pragma unroll
        for (int it = 0; it < 2; it++) {
            int i = tid + it * AT_THREADS;
            int n = i >> 2, c16 = i & 3;
            asm volatile("cp.async.cg.shared.global [%0], [%1], 16;"
                         :: "r"(dstb + (uint32_t)(n * HSTRH * 2 + c16 * 16)),
                            "l"(src + (size_t)n * NN + c16 * 8));
        }
        asm volatile("cp.async.commit_group;");
    }

    // ---- per-row constants ----
    float f1p[4], f1n[4];
    const uint32_t* mrow[4];
#pragma unroll
    for (int r = 0; r < 4; r++) {
        int grow = row0 + wid * 32 + q + r * 8;
        float2 e = g_e1[grow];
        f1p[r] = e.x; f1n[r] = e.y;
        mrow[r] = g_mask + (size_t)grow * 256 + kh * 128;
    }
    uint32_t mcur[4];
#pragma unroll
    for (int r = 0; r < 4; r++) mcur[r] = mrow[r][0];

    float acc[2][17][4];
#pragma unroll
    for (int g = 0; g < 2; g++)
#pragma unroll
        for (int nb = 0; nb < 17; nb++)
#pragma unroll
            for (int j = 0; j < 4; j++) acc[g][nb][j] = 0.f;

    for (int t = 0; t < ATILES; t++) {
        if (t + 1 < ATILES) {
            uint32_t dstb = smem_u32(HsB[(t + 1) & 1]);
            const __half* src = g_hT + (size_t)nbase * NN + kbase + (t + 1) * KT;
#pragma unroll
            for (int it = 0; it < 2; it++) {
                int i = tid + it * AT_THREADS;
                int n = i >> 2, c16 = i & 3;
                asm volatile("cp.async.cg.shared.global [%0], [%1], 16;"
                             :: "r"(dstb + (uint32_t)(n * HSTRH * 2 + c16 * 16)),
                                "l"(src + (size_t)n * NN + c16 * 8));
            }
            asm volatile("cp.async.commit_group;");
            asm volatile("cp.async.wait_group 1;");
        } else {
            asm volatile("cp.async.wait_group 0;");
        }
        __syncthreads();

        uint32_t mnext[4] = {0, 0, 0, 0};
        if (t + 1 < ATILES) {
#pragma unroll
            for (int r = 0; r < 4; r++) mnext[r] = mrow[r][t + 1];
        }

        const __half* Hb = HsB[t & 1];
        const int kl0 = t * KT;

#pragma unroll
        for (int c = 0; c < 2; c++) {           // two k16 chunks
            const int kc = c * 16 + 2 * tc;
            float2 eL0 = e2sm[kl0 + kc];
            float2 eL1 = e2sm[kl0 + kc + 1];
            float2 eH0 = e2sm[kl0 + kc + 8];
            float2 eH1 = e2sm[kl0 + kc + 9];
            const uint32_t bL0 = 1u << kc,      bL1 = 2u << kc;
            const uint32_t bH0 = 256u << kc,    bH1 = 512u << kc;

            uint32_t aL[4], aH[4];
#pragma unroll
            for (int r = 0; r < 4; r++) {
                float pL0 = fmaxf(f1p[r] * eL0.x, f1n[r] * eL0.y);
                float pL1 = fmaxf(f1p[r] * eL1.x, f1n[r] * eL1.y);
                float pH0 = fmaxf(f1p[r] * eH0.x, f1n[r] * eH0.y);
                float pH1 = fmaxf(f1p[r] * eH1.x, f1n[r] * eH1.y);
                pL0 = (mcur[r] & bL0) ? pL0 : 0.f;
                pL1 = (mcur[r] & bL1) ? pL1 : 0.f;
                pH0 = (mcur[r] & bH0) ? pH0 : 0.f;
                pH1 = (mcur[r] & bH1) ? pH1 : 0.f;
                aL[r] = f16x2_pack(pL1, pL0);
                aH[r] = f16x2_pack(pH1, pH0);
            }

            const __half* bp = Hb + q * HSTRH + c * 16 + 2 * tc;
#pragma unroll
            for (int nb = 0; nb < 17; nb++) {
                uint32_t b0 = *(const uint32_t*)(bp + nb * 8 * HSTRH);
                uint32_t b1 = *(const uint32_t*)(bp + nb * 8 * HSTRH + 8);
                asm volatile(
                    "mma.sync.aligned.m16n8k16.row.col.f32.f16.f16.f32 "
                    "{%0,%1,%2,%3}, {%4,%5,%6,%7}, {%8,%9}, {%0,%1,%2,%3};"
                    : "+f"(acc[0][nb][0]), "+f"(acc[0][nb][1]),
                      "+f"(acc[0][nb][2]), "+f"(acc[0][nb][3])
                    : "r"(aL[0]), "r"(aL[1]), "r"(aH[0]), "r"(aH[1]),
                      "r"(b0), "r"(b1));
                asm volatile(
                    "mma.sync.aligned.m16n8k16.row.col.f32.f16.f16.f32 "
                    "{%0,%1,%2,%3}, {%4,%5,%6,%7}, {%8,%9}, {%0,%1,%2,%3};"
                    : "+f"(acc[1][nb][0]), "+f"(acc[1][nb][1]),
                      "+f"(acc[1][nb][2]), "+f"(acc[1][nb][3])
                    : "r"(aL[2]), "r"(aL[3]), "r"(aH[2]), "r"(aH[3]),
                      "r"(b0), "r"(b1));
            }
        }
        __syncthreads();

#pragma unroll
        for (int r = 0; r < 4; r++) mcur[r] = mnext[r];
    }

    // ---- store partial D + z ----
    float* dp = g_dpart + (size_t)kh * NN * FOUT;
#pragma unroll
    for (int g = 0; g < 2; g++) {
        const int rlo = row0 + wid * 32 + g * 16 + q;
        const int rhi = rlo + 8;
#pragma unroll
        for (int nb = 0; nb < 16; nb++) {
            int c = nbase + nb * 8 + tc * 2;
            *(float2*)&dp[(size_t)rlo * FOUT + c] = make_float2(acc[g][nb][0], acc[g][nb][1]);
            *(float2*)&dp[(size_t)rhi * FOUT + c] = make_float2(acc[g][nb][2], acc[g][nb][3]);
        }
        if (nh == 0 && tc == 0) {
            g_z[kh * NN + rlo] = acc[g][16][0];
            g_z[kh * NN + rhi] = acc[g][16][2];
        }
    }
}

// ============================================================
// Kernel 4: combine K-split partials, normalize, ELU
// ============================================================
__global__ __launch_bounds__(256) void combine_kernel(float* __restrict__ out)
{
    int idx = blockIdx.x * 256 + threadIdx.x;
    const float4* d0 = (const float4*)g_dpart;
    const float4* d1 = d0 + (NN * FOUT / 4);
    float4 a = d0[idx], b = d1[idx];
    int row = idx >> 6;
    float inv = 1.0f / (g_z[row] + g_z[NN + row]);
    float4 o; float t;
    t = (a.x + b.x) * inv; o.x = (t > 0.f) ? t : expm1f(t);
    t = (a.y + b.y) * inv; o.y = (t > 0.f) ? t : expm1f(t);
    t = (a.z + b.z) * inv; o.z = (t > 0.f) ? t : expm1f(t);
    t = (a.w + b.w) * inv; o.w = (t > 0.f) ? t : expm1f(t);
    ((float4*)out)[idx] = o;
}

// ============================================================
// launch
// ============================================================
extern "C" void kernel_launch(void* const* d_in, const int* in_sizes, int n_in,
                              void* d_out, int out_size)
{
    const float* input = (const float*)d_in[0];   // [8192, 512]
    const int*   adj   = (const int*)  d_in[1];   // [8192, 8192]
    const float* W     = (const float*)d_in[2];   // [512, 256]
    const float* a     = (const float*)d_in[3];   // [512, 1]
    float* out = (float*)d_out;                   // [8192, 256]

    float* h;
    __half* hT;
    uint32_t* mask;
    cudaGetSymbolAddress((void**)&h, g_h);
    cudaGetSymbolAddress((void**)&hT, g_hT);
    cudaGetSymbolAddress((void**)&mask, g_mask);

    cudaFuncSetAttribute(attn_kernel, cudaFuncAttributeMaxDynamicSharedMemorySize, AT_SMEM);

    gemm_h_kernel<<<dim3(NN / G1_BM, FOUT / G1_BN), 256>>>(input, W, h);
    s_kernel<<<NN / 8, 256>>>(h, a);
    prep_kernel<<<1, 256>>>();
    t_kernel<<<dim3(NN / 32, FOUT / 32), 256>>>(h, hT);
    pack_kernel<<<NN, 256>>>(adj, mask);
    attn_kernel<<<128, AT_THREADS, AT_SMEM>>>();
    combine_kernel<<<NN * FOUT / 4 / 256, 256>>>(out);
}